// round 7
// baseline (speedup 1.0000x reference)
#include <cuda_runtime.h>
#include <cuda_fp16.h>
#include <cstdint>

// ---------------------------------------------------------------------------
// SAGE_37203006718147: 3-layer GraphSAGE on sm_103a.
// Features kept as fp16 mirrors (x16, h1_16, h2_16): gather traffic halved,
// x16 fits L2. Per layer (fork-join on two captured streams):
//   [default] edge-aggregation(fp16 gather, fp32 atomics)
//   [s2]      self-GEMM  h16@Ws + b -> fp32 partial
//   join ->   neigh-GEMM partial + (agg/deg)@Wn (+relu) -> fp16 h (fp32 for L2)
// GEMM: mma.sync fp16, fp32 accumulate. tcgen05 unavailable (harness compiles
// at virtual arch compute_103, no 'a').
// ---------------------------------------------------------------------------

#define N0C 200000
#define N1C 50000
#define N2C 12000
#define N3C 3000
#define DF  256

// ---- scratch (static device allocations; cudaMalloc forbidden) ----
__device__ float  g_agg0[N1C * DF];
__device__ float  g_deg0[N1C];
__device__ float  g_agg1[N2C * DF];
__device__ float  g_deg1[N2C];
__device__ float  g_agg2[N3C * DF];
__device__ float  g_deg2[N3C];
__device__ __half g_x16 [N0C * DF];
__device__ __half g_h1x [N1C * DF];   // fp16 h1
__device__ __half g_h2x [N2C * DF];   // fp16 h2
__device__ float  g_p1  [N1C * DF];   // fp32 self partial, layer 0
__device__ float  g_p2  [N2C * DF];   // fp32 self partial, layer 1
// transposed fp16 weights: [N][K=512] = [Ws ; Wn], K-major
__device__ __half g_wt0[256 * 512];
__device__ __half g_wt1[256 * 512];
__device__ __half g_wt2[64 * 512];

// ---------------------------------------------------------------------------
// helpers
// ---------------------------------------------------------------------------
__device__ __forceinline__ uint32_t smem_u32(const void* p) {
    uint32_t a;
    asm("{ .reg .u64 t; cvta.to.shared.u64 t, %1; cvt.u32.u64 %0, t; }"
        : "=r"(a) : "l"(p));
    return a;
}

__device__ __forceinline__ void ldsm4(uint32_t* r, uint32_t addr) {
    asm volatile("ldmatrix.sync.aligned.m8n8.x4.shared.b16 {%0,%1,%2,%3}, [%4];"
                 : "=r"(r[0]), "=r"(r[1]), "=r"(r[2]), "=r"(r[3]) : "r"(addr));
}

__device__ __forceinline__ void mma16816(float* c, const uint32_t* a,
                                         const uint32_t* b) {
    asm volatile(
        "mma.sync.aligned.m16n8k16.row.col.f32.f16.f16.f32 "
        "{%0,%1,%2,%3}, {%4,%5,%6,%7}, {%8,%9}, {%0,%1,%2,%3};"
        : "+f"(c[0]), "+f"(c[1]), "+f"(c[2]), "+f"(c[3])
        : "r"(a[0]), "r"(a[1]), "r"(a[2]), "r"(a[3]), "r"(b[0]), "r"(b[1]));
}

// convert 8 fp32 -> 8 packed fp16 (uint4)
__device__ __forceinline__ uint4 cvt8(float4 a, float4 b) {
    float f[8] = {a.x, a.y, a.z, a.w, b.x, b.y, b.z, b.w};
    uint32_t H[8];
#pragma unroll
    for (int i = 0; i < 8; i++)
        H[i] = (uint32_t)__half_as_ushort(__float2half_rn(f[i]));
    uint4 r;
    r.x = H[0] | (H[1] << 16); r.y = H[2] | (H[3] << 16);
    r.z = H[4] | (H[5] << 16); r.w = H[6] | (H[7] << 16);
    return r;
}

// ---------------------------------------------------------------------------
// fp32 -> fp16 bulk convert (8 elems/thread)
// ---------------------------------------------------------------------------
__global__ void convert_fp16(const float* __restrict__ in,
                             __half* __restrict__ out, int n8)
{
    int i = blockIdx.x * blockDim.x + threadIdx.x;
    if (i >= n8) return;
    float4 a = __ldg((const float4*)in + 2 * i);
    float4 b = __ldg((const float4*)in + 2 * i + 1);
    ((uint4*)out)[i] = cvt8(a, b);
}

// ---------------------------------------------------------------------------
// Weight prep: Wt[n][k] = fp16(k<256 ? Ws[k][n] : Wn[k-256][n]), K-major
// ---------------------------------------------------------------------------
__global__ void convert_weights(const float* __restrict__ Ws,
                                const float* __restrict__ Wn,
                                __half* __restrict__ wt, int NC)
{
    int idx = blockIdx.x * blockDim.x + threadIdx.x;
    if (idx >= NC * 512) return;
    int n = idx >> 9, k = idx & 511;
    float v = (k < 256) ? Ws[(size_t)k * NC + n] : Wn[(size_t)(k - 256) * NC + n];
    wt[idx] = __float2half_rn(v);
}

// ---------------------------------------------------------------------------
// Edge aggregation (fp16 gather): 4 edges/warp; each lane gathers one uint4
// (8 halves) per edge, converts to fp32, vector red.global.add.
// ---------------------------------------------------------------------------
__global__ void sage_aggregate16(const __half* __restrict__ h16,
                                 const int*   __restrict__ src,
                                 const int*   __restrict__ dst,
                                 float*       __restrict__ agg,
                                 float*       __restrict__ deg,
                                 int E)
{
    int warp = (int)(blockIdx.x * (blockDim.x >> 5) + (threadIdx.x >> 5));
    int lane = threadIdx.x & 31;
    int e0 = warp * 4;
    if (e0 >= E) return;
    int n = E - e0;
    if (n > 4) n = 4;

    int s[4], d[4];
#pragma unroll
    for (int e = 0; e < 4; e++) {
        int idx = (e < n) ? e0 + e : e0;
        s[e] = __ldg(src + idx);
        d[e] = __ldg(dst + idx);
    }
    uint4 v[4];
#pragma unroll
    for (int e = 0; e < 4; e++)
        if (e < n)
            v[e] = __ldg((const uint4*)(h16 + (size_t)s[e] * DF) + lane);

#pragma unroll
    for (int e = 0; e < 4; e++) {
        if (e < n) {
            float2 f0 = __half22float2(*(__half2*)&v[e].x);
            float2 f1 = __half22float2(*(__half2*)&v[e].y);
            float2 f2 = __half22float2(*(__half2*)&v[e].z);
            float2 f3 = __half22float2(*(__half2*)&v[e].w);
            float* p = agg + (size_t)d[e] * DF + lane * 8;
            asm volatile("red.global.add.v4.f32 [%0], {%1, %2, %3, %4};"
                         :: "l"(p), "f"(f0.x), "f"(f0.y), "f"(f1.x), "f"(f1.y)
                         : "memory");
            asm volatile("red.global.add.v4.f32 [%0], {%1, %2, %3, %4};"
                         :: "l"(p + 4), "f"(f2.x), "f"(f2.y), "f"(f3.x), "f"(f3.y)
                         : "memory");
        }
    }
#pragma unroll
    for (int e = 0; e < 4; e++)
        if (lane == e && e < n) atomicAdd(deg + d[e], 1.0f);
}

// ---------------------------------------------------------------------------
// Self GEMM: part[m, bn] = h16[m, 0:256] @ Ws^T + b.  A fp16 via cp.async.
// 8 warps (4x2), warp tile 32x(BN/2), BK=32, double-buffered.
// ---------------------------------------------------------------------------
template<int BN>
__global__ __launch_bounds__(256)
void sage_gemm_self16(const __half* __restrict__ A16,
                      const __half* __restrict__ wt,
                      const float* __restrict__ bias,
                      float* __restrict__ out, int M, int NCOLS)
{
    constexpr int APITCH = 80;
    constexpr int ASTG   = 128 * APITCH;
    constexpr int BSTG   = BN * APITCH;
    constexpr int SS     = ASTG + BSTG;
    constexpr int NT8    = BN / 16;
    constexpr int NBSEG  = (BN * 4) / 256;
    constexpr int WN     = BN / 2;

    extern __shared__ char smem[];
    char* stg = smem + 1024;
    uint32_t stg_u = smem_u32(stg);

    int tid  = threadIdx.x;
    int lane = tid & 31, wid = tid >> 5;
    int wm = wid & 3, wn = wid >> 2;
    int bm0 = blockIdx.y * 128, bn0 = blockIdx.x * BN;

    auto issueAB = [&](int kt, int s) {
        int kc = kt * 32;
        uint32_t abase = stg_u + s * SS;
        // A: 128 rows x 32 halves (64B) = 512 x 16B segs
#pragma unroll
        for (int i = 0; i < 2; i++) {
            int seg = tid + 256 * i;
            int row = seg >> 2, cc = (seg & 3) * 16;
            uint32_t sa = abase + row * APITCH + cc;
            const __half* g = A16 + (size_t)(bm0 + row) * DF + kc + (seg & 3) * 8;
            int sz = (bm0 + row < M) ? 16 : 0;
            asm volatile("cp.async.cg.shared.global [%0], [%1], 16, %2;"
                         :: "r"(sa), "l"(g), "r"(sz));
        }
        uint32_t bbase = abase + ASTG;
#pragma unroll
        for (int i = 0; i < NBSEG; i++) {
            int seg = tid + 256 * i;
            int row = seg >> 2, cc = (seg & 3) * 16;
            uint32_t sa = bbase + row * APITCH + cc;
            const __half* g = wt + (size_t)(bn0 + row) * 512 + kc + (seg & 3) * 8;
            asm volatile("cp.async.cg.shared.global [%0], [%1], 16;"
                         :: "r"(sa), "l"(g));
        }
        asm volatile("cp.async.commit_group;" ::: "memory");
    };

    float acc[2][NT8][4] = {};

    issueAB(0, 0);

#pragma unroll 1
    for (int kt = 0; kt < 8; kt++) {
        int s = kt & 1;
        asm volatile("cp.async.wait_group 0;" ::: "memory");
        __syncthreads();
        if (kt < 7) issueAB(kt + 1, 1 - s);

        uint32_t abase = stg_u + s * SS;
        uint32_t bbase = abase + ASTG;
#pragma unroll
        for (int ks = 0; ks < 2; ks++) {
            uint32_t af[2][4], bf[NT8][2];
#pragma unroll
            for (int mt = 0; mt < 2; mt++) {
                int r  = wm * 32 + mt * 16 + (lane & 7) + ((lane >> 3) & 1) * 8;
                int kb = ks * 16 + ((lane >> 4) & 1) * 8;
                ldsm4(af[mt], abase + r * APITCH + kb * 2);
            }
#pragma unroll
            for (int p = 0; p < NT8 / 2; p++) {
                int n  = wn * WN + p * 16 + (lane & 7) + ((lane >> 4) & 1) * 8;
                int kb = ks * 16 + ((lane >> 3) & 1) * 8;
                uint32_t th[4];
                ldsm4(th, bbase + n * APITCH + kb * 2);
                bf[2 * p][0] = th[0]; bf[2 * p][1] = th[1];
                bf[2 * p + 1][0] = th[2]; bf[2 * p + 1][1] = th[3];
            }
#pragma unroll
            for (int mt = 0; mt < 2; mt++)
#pragma unroll
                for (int nt = 0; nt < NT8; nt++)
                    mma16816(acc[mt][nt], af[mt], bf[nt]);
        }
        __syncthreads();
    }

#pragma unroll
    for (int mt = 0; mt < 2; mt++) {
        int r0 = bm0 + wm * 32 + mt * 16 + (lane >> 2);
#pragma unroll
        for (int nt = 0; nt < NT8; nt++) {
            int col = bn0 + wn * WN + nt * 8 + (lane & 3) * 2;
            float2 bv = *(const float2*)(bias + col);
            float2 o0, o1;
            o0.x = acc[mt][nt][0] + bv.x; o0.y = acc[mt][nt][1] + bv.y;
            o1.x = acc[mt][nt][2] + bv.x; o1.y = acc[mt][nt][3] + bv.y;
            if (r0 < M)
                *(float2*)(out + (size_t)r0 * NCOLS + col) = o0;
            if (r0 + 8 < M)
                *(float2*)(out + (size_t)(r0 + 8) * NCOLS + col) = o1;
        }
    }
}

// ---------------------------------------------------------------------------
// Neigh GEMM: final = part + (agg/deg)@Wn (+relu); writes fp16 (OUT16) or
// fp32. A fp32 staged through regs (deg scale + fp16 quantize).
// ---------------------------------------------------------------------------
template<int BN, bool RELU, bool OUT16>
__global__ __launch_bounds__(256)
void sage_gemm_neigh(const float* __restrict__ agg,
                     const float* __restrict__ deg,
                     const __half* __restrict__ wt,
                     const float* __restrict__ part,
                     float* __restrict__ out32,
                     __half* __restrict__ out16,
                     int M, int NCOLS)
{
    constexpr int APITCH = 80;
    constexpr int ASTG   = 128 * APITCH;
    constexpr int BSTG   = BN * APITCH;
    constexpr int SS     = ASTG + BSTG;
    constexpr int NT8    = BN / 16;
    constexpr int NBSEG  = (BN * 4) / 256;
    constexpr int WN     = BN / 2;

    extern __shared__ char smem[];
    float* s_invd = (float*)smem;
    char*  stg    = smem + 1024;
    uint32_t stg_u = smem_u32(stg);

    int tid  = threadIdx.x;
    int lane = tid & 31, wid = tid >> 5;
    int wm = wid & 3, wn = wid >> 2;
    int bm0 = blockIdx.y * 128, bn0 = blockIdx.x * BN;

    if (tid < 128) {
        int r = bm0 + tid;
        float dg = (r < M) ? deg[r] : 1.0f;
        s_invd[tid] = 1.0f / fmaxf(dg, 1.0f);
    }
    __syncthreads();

    uint4 ah[2];

    auto prepA = [&](int kt) {
        int kc = kt * 32;
#pragma unroll
        for (int i = 0; i < 2; i++) {
            int seg = tid + 256 * i;
            int row = seg >> 2, c8 = (seg & 3) * 8;
            int gr = bm0 + row;
            float4 v0 = make_float4(0.f, 0.f, 0.f, 0.f), v1 = v0;
            if (gr < M) {
                const float4* p = (const float4*)(agg + (size_t)gr * DF + kc + c8);
                v0 = __ldg(p); v1 = __ldg(p + 1);
                float sc = s_invd[row];
                v0.x *= sc; v0.y *= sc; v0.z *= sc; v0.w *= sc;
                v1.x *= sc; v1.y *= sc; v1.z *= sc; v1.w *= sc;
            }
            ah[i] = cvt8(v0, v1);
        }
    };

    auto storeA = [&](int s) {
        char* base = stg + s * SS;
#pragma unroll
        for (int i = 0; i < 2; i++) {
            int seg = tid + 256 * i;
            int row = seg >> 2, cc = (seg & 3) * 16;
            *(uint4*)(base + row * APITCH + cc) = ah[i];
        }
    };

    auto issueB = [&](int kt, int s) {
        int kg = kt * 32;
        uint32_t bbase = stg_u + s * SS + ASTG;
#pragma unroll
        for (int i = 0; i < NBSEG; i++) {
            int seg = tid + 256 * i;
            int row = seg >> 2, cc = (seg & 3) * 16;
            uint32_t sa = bbase + row * APITCH + cc;
            const __half* g = wt + (size_t)(bn0 + row) * 512 + 256 + kg + (seg & 3) * 8;
            asm volatile("cp.async.cg.shared.global [%0], [%1], 16;"
                         :: "r"(sa), "l"(g));
        }
        asm volatile("cp.async.commit_group;" ::: "memory");
    };

    float acc[2][NT8][4] = {};

    issueB(0, 0);
    prepA(0);

#pragma unroll 1
    for (int kt = 0; kt < 8; kt++) {
        int s = kt & 1;
        storeA(s);
        asm volatile("cp.async.wait_group 0;" ::: "memory");
        __syncthreads();
        if (kt < 7) {
            issueB(kt + 1, 1 - s);
            prepA(kt + 1);
        }

        uint32_t abase = stg_u + s * SS;
        uint32_t bbase = abase + ASTG;
#pragma unroll
        for (int ks = 0; ks < 2; ks++) {
            uint32_t af[2][4], bf[NT8][2];
#pragma unroll
            for (int mt = 0; mt < 2; mt++) {
                int r  = wm * 32 + mt * 16 + (lane & 7) + ((lane >> 3) & 1) * 8;
                int kb = ks * 16 + ((lane >> 4) & 1) * 8;
                ldsm4(af[mt], abase + r * APITCH + kb * 2);
            }
#pragma unroll
            for (int p = 0; p < NT8 / 2; p++) {
                int n  = wn * WN + p * 16 + (lane & 7) + ((lane >> 4) & 1) * 8;
                int kb = ks * 16 + ((lane >> 3) & 1) * 8;
                uint32_t th[4];
                ldsm4(th, bbase + n * APITCH + kb * 2);
                bf[2 * p][0] = th[0]; bf[2 * p][1] = th[1];
                bf[2 * p + 1][0] = th[2]; bf[2 * p + 1][1] = th[3];
            }
#pragma unroll
            for (int mt = 0; mt < 2; mt++)
#pragma unroll
                for (int nt = 0; nt < NT8; nt++)
                    mma16816(acc[mt][nt], af[mt], bf[nt]);
        }
    }

    // ---- epilogue: add partial, relu?, store fp16/fp32 ----
#pragma unroll
    for (int mt = 0; mt < 2; mt++) {
        int r0 = bm0 + wm * 32 + mt * 16 + (lane >> 2);
#pragma unroll
        for (int nt = 0; nt < NT8; nt++) {
            int col = bn0 + wn * WN + nt * 8 + (lane & 3) * 2;
            float2 o0 = make_float2(acc[mt][nt][0], acc[mt][nt][1]);
            float2 o1 = make_float2(acc[mt][nt][2], acc[mt][nt][3]);
            if (r0 < M) {
                float2 e = *(const float2*)(part + (size_t)r0 * NCOLS + col);
                o0.x += e.x; o0.y += e.y;
            }
            if (r0 + 8 < M) {
                float2 e = *(const float2*)(part + (size_t)(r0 + 8) * NCOLS + col);
                o1.x += e.x; o1.y += e.y;
            }
            if (RELU) {
                o0.x = fmaxf(o0.x, 0.f); o0.y = fmaxf(o0.y, 0.f);
                o1.x = fmaxf(o1.x, 0.f); o1.y = fmaxf(o1.y, 0.f);
            }
            if (OUT16) {
                if (r0 < M)
                    *(__half2*)(out16 + (size_t)r0 * NCOLS + col) =
                        __floats2half2_rn(o0.x, o0.y);
                if (r0 + 8 < M)
                    *(__half2*)(out16 + (size_t)(r0 + 8) * NCOLS + col) =
                        __floats2half2_rn(o1.x, o1.y);
            } else {
                if (r0 < M)
                    *(float2*)(out32 + (size_t)r0 * NCOLS + col) = o0;
                if (r0 + 8 < M)
                    *(float2*)(out32 + (size_t)(r0 + 8) * NCOLS + col) = o1;
            }
        }
    }
}

// ---------------------------------------------------------------------------
// Launch: prep on s2 overlapping convert_x; per layer fork-join.
// ---------------------------------------------------------------------------
extern "C" void kernel_launch(void* const* d_in, const int* in_sizes, int n_in,
                              void* d_out, int out_size)
{
    const float* x    = (const float*)d_in[0];
    const int*   src0 = (const int*)d_in[1];
    const int*   dst0 = (const int*)d_in[2];
    const int*   src1 = (const int*)d_in[3];
    const int*   dst1 = (const int*)d_in[4];
    const int*   src2 = (const int*)d_in[5];
    const int*   dst2 = (const int*)d_in[6];

    int wb = n_in - 9;
    const float* Ws0 = (const float*)d_in[wb + 0];
    const float* Wn0 = (const float*)d_in[wb + 1];
    const float* b0  = (const float*)d_in[wb + 2];
    const float* Ws1 = (const float*)d_in[wb + 3];
    const float* Wn1 = (const float*)d_in[wb + 4];
    const float* b1  = (const float*)d_in[wb + 5];
    const float* Ws2 = (const float*)d_in[wb + 6];
    const float* Wn2 = (const float*)d_in[wb + 7];
    const float* b2  = (const float*)d_in[wb + 8];

    int E0 = in_sizes[1];
    int E1 = in_sizes[3];
    int E2 = in_sizes[5];
    int xN = in_sizes[0];   // N0*256

    float *agg0, *deg0, *agg1, *deg1, *agg2, *deg2, *p1, *p2;
    __half *x16, *h1x, *h2x, *wt0, *wt1, *wt2;
    cudaGetSymbolAddress((void**)&agg0, g_agg0);
    cudaGetSymbolAddress((void**)&deg0, g_deg0);
    cudaGetSymbolAddress((void**)&agg1, g_agg1);
    cudaGetSymbolAddress((void**)&deg1, g_deg1);
    cudaGetSymbolAddress((void**)&agg2, g_agg2);
    cudaGetSymbolAddress((void**)&deg2, g_deg2);
    cudaGetSymbolAddress((void**)&p1,   g_p1);
    cudaGetSymbolAddress((void**)&p2,   g_p2);
    cudaGetSymbolAddress((void**)&x16,  g_x16);
    cudaGetSymbolAddress((void**)&h1x,  g_h1x);
    cudaGetSymbolAddress((void**)&h2x,  g_h2x);
    cudaGetSymbolAddress((void**)&wt0,  g_wt0);
    cudaGetSymbolAddress((void**)&wt1,  g_wt1);
    cudaGetSymbolAddress((void**)&wt2,  g_wt2);

    const int SMEM128 = 1024 + 2 * (128 * 80 + 128 * 80);  // 41984
    const int SMEM64  = 1024 + 2 * (128 * 80 + 64 * 80);   // 31744
    cudaFuncSetAttribute(sage_gemm_self16<128>,
                         cudaFuncAttributeMaxDynamicSharedMemorySize, SMEM128);
    cudaFuncSetAttribute(sage_gemm_self16<64>,
                         cudaFuncAttributeMaxDynamicSharedMemorySize, SMEM64);
    cudaFuncSetAttribute(sage_gemm_neigh<128, false, true>,
                         cudaFuncAttributeMaxDynamicSharedMemorySize, SMEM128);
    cudaFuncSetAttribute(sage_gemm_neigh<128, true, true>,
                         cudaFuncAttributeMaxDynamicSharedMemorySize, SMEM128);
    cudaFuncSetAttribute(sage_gemm_neigh<64, false, false>,
                         cudaFuncAttributeMaxDynamicSharedMemorySize, SMEM64);

    cudaStream_t s2;
    cudaStreamCreateWithFlags(&s2, cudaStreamNonBlocking);
    cudaEvent_t evStart, evX, evPrep, evJ0, evF1, evJ1, evF2, evJ2;
    cudaEventCreateWithFlags(&evStart, cudaEventDisableTiming);
    cudaEventCreateWithFlags(&evX,     cudaEventDisableTiming);
    cudaEventCreateWithFlags(&evPrep,  cudaEventDisableTiming);
    cudaEventCreateWithFlags(&evJ0,    cudaEventDisableTiming);
    cudaEventCreateWithFlags(&evF1,    cudaEventDisableTiming);
    cudaEventCreateWithFlags(&evJ1,    cudaEventDisableTiming);
    cudaEventCreateWithFlags(&evF2,    cudaEventDisableTiming);
    cudaEventCreateWithFlags(&evJ2,    cudaEventDisableTiming);

    // fork: s2 does weight converts + memsets while default does convert_x
    cudaEventRecord(evStart, 0);
    cudaStreamWaitEvent(s2, evStart, 0);

    convert_fp16<<<(xN / 8 + 255) / 256, 256>>>(x, x16, xN / 8);
    cudaEventRecord(evX, 0);

    convert_weights<<<(256 * 512 + 255) / 256, 256, 0, s2>>>(Ws0, Wn0, wt0, 256);
    convert_weights<<<(256 * 512 + 255) / 256, 256, 0, s2>>>(Ws1, Wn1, wt1, 256);
    convert_weights<<<(64  * 512 + 255) / 256, 256, 0, s2>>>(Ws2, Wn2, wt2, 64);
    cudaMemsetAsync(agg0, 0, sizeof(float) * (size_t)N1C * DF, s2);
    cudaMemsetAsync(deg0, 0, sizeof(float) * N1C, s2);
    cudaMemsetAsync(agg1, 0, sizeof(float) * (size_t)N2C * DF, s2);
    cudaMemsetAsync(deg1, 0, sizeof(float) * N2C, s2);
    cudaMemsetAsync(agg2, 0, sizeof(float) * (size_t)N3C * DF, s2);
    cudaMemsetAsync(deg2, 0, sizeof(float) * N3C, s2);
    cudaEventRecord(evPrep, s2);

    // ---- Layer 0 ----
    cudaStreamWaitEvent(0, evPrep, 0);
    sage_aggregate16<<<(E0 + 31) / 32, 256>>>(x16, src0, dst0, agg0, deg0, E0);
    cudaStreamWaitEvent(s2, evX, 0);     // self0 needs x16
    sage_gemm_self16<128><<<dim3(2, (N1C + 127) / 128), 256, SMEM128, s2>>>(
        x16, wt0, b0, p1, N1C, 256);
    cudaEventRecord(evJ0, s2);
    cudaStreamWaitEvent(0, evJ0, 0);
    sage_gemm_neigh<128, false, true><<<dim3(2, (N1C + 127) / 128), 256, SMEM128>>>(
        agg0, deg0, wt0, p1, nullptr, h1x, N1C, 256);
    cudaEventRecord(evF1, 0);

    // ---- Layer 1 (relu) ----
    sage_aggregate16<<<(E1 + 31) / 32, 256>>>(h1x, src1, dst1, agg1, deg1, E1);
    cudaStreamWaitEvent(s2, evF1, 0);    // self1 needs h1x
    sage_gemm_self16<128><<<dim3(2, (N2C + 127) / 128), 256, SMEM128, s2>>>(
        h1x, wt1, b1, p2, N2C, 256);
    cudaEventRecord(evJ1, s2);
    cudaStreamWaitEvent(0, evJ1, 0);
    sage_gemm_neigh<128, true, true><<<dim3(2, (N2C + 127) / 128), 256, SMEM128>>>(
        agg1, deg1, wt1, p2, nullptr, h2x, N2C, 256);
    cudaEventRecord(evF2, 0);

    // ---- Layer 2 (fp32 out) ----
    sage_aggregate16<<<(E2 + 31) / 32, 256>>>(h2x, src2, dst2, agg2, deg2, E2);
    cudaStreamWaitEvent(s2, evF2, 0);    // self2 needs h2x
    sage_gemm_self16<64><<<dim3(1, (N3C + 127) / 128), 256, SMEM64, s2>>>(
        h2x, wt2, b2, (float*)d_out, N3C, 64);
    cudaEventRecord(evJ2, s2);
    cudaStreamWaitEvent(0, evJ2, 0);
    sage_gemm_neigh<64, false, false><<<dim3(1, (N3C + 127) / 128), 256, SMEM64>>>(
        agg2, deg2, wt2, (float*)d_out, (float*)d_out, nullptr, N3C, 64);
}

// round 8
// speedup vs baseline: 1.2847x; 1.2847x over previous
#include <cuda_runtime.h>
#include <cuda_fp16.h>
#include <cstdint>

// ---------------------------------------------------------------------------
// SAGE_37203006718147: 3-layer GraphSAGE on sm_103a.
// Per layer (fork-join on two captured streams):
//   [default] edge-aggregation (fp32 gather, vector RED)   ||  [s2] self-GEMM
//   join -> [default] neigh-GEMM: out += (agg/deg)@Wn (+relu)
// GEMM: mma.sync fp16 1-term, fp32 accumulate, BK=64 double-buffered.
// Single contiguous scratch (1 memset node) + fused weight convert.
// tcgen05 unavailable: harness compiles at virtual arch compute_103 (no 'a').
// ---------------------------------------------------------------------------

#define N1C 50000
#define N2C 12000
#define N3C 3000
#define DF  256

// ---- contiguous scratch: agg0|agg1|agg2|deg0|deg1|deg2 (one memset) ----
#define AGG0_OFF 0
#define AGG1_OFF (N1C * DF)
#define AGG2_OFF (AGG1_OFF + N2C * DF)
#define DEG0_OFF (AGG2_OFF + N3C * DF)
#define DEG1_OFF (DEG0_OFF + N1C)
#define DEG2_OFF (DEG1_OFF + N2C)
#define SCR_TOT  (DEG2_OFF + N3C)

__device__ float  g_scr[SCR_TOT];
__device__ float  g_h1 [N1C * DF];
__device__ float  g_h2 [N2C * DF];
// transposed fp16 weights: [N][K=512] = [Ws ; Wn], K-major
__device__ __half g_wt0[256 * 512];
__device__ __half g_wt1[256 * 512];
__device__ __half g_wt2[64 * 512];

// ---------------------------------------------------------------------------
// helpers
// ---------------------------------------------------------------------------
__device__ __forceinline__ uint32_t smem_u32(const void* p) {
    uint32_t a;
    asm("{ .reg .u64 t; cvta.to.shared.u64 t, %1; cvt.u32.u64 %0, t; }"
        : "=r"(a) : "l"(p));
    return a;
}

__device__ __forceinline__ void ldsm4(uint32_t* r, uint32_t addr) {
    asm volatile("ldmatrix.sync.aligned.m8n8.x4.shared.b16 {%0,%1,%2,%3}, [%4];"
                 : "=r"(r[0]), "=r"(r[1]), "=r"(r[2]), "=r"(r[3]) : "r"(addr));
}

__device__ __forceinline__ void mma16816(float* c, const uint32_t* a,
                                         const uint32_t* b) {
    asm volatile(
        "mma.sync.aligned.m16n8k16.row.col.f32.f16.f16.f32 "
        "{%0,%1,%2,%3}, {%4,%5,%6,%7}, {%8,%9}, {%0,%1,%2,%3};"
        : "+f"(c[0]), "+f"(c[1]), "+f"(c[2]), "+f"(c[3])
        : "r"(a[0]), "r"(a[1]), "r"(a[2]), "r"(a[3]), "r"(b[0]), "r"(b[1]));
}

// convert 8 fp32 -> 8 packed fp16 (uint4)
__device__ __forceinline__ uint4 cvt8(float4 a, float4 b) {
    float f[8] = {a.x, a.y, a.z, a.w, b.x, b.y, b.z, b.w};
    uint32_t H[8];
#pragma unroll
    for (int i = 0; i < 8; i++)
        H[i] = (uint32_t)__half_as_ushort(__float2half_rn(f[i]));
    uint4 r;
    r.x = H[0] | (H[1] << 16); r.y = H[2] | (H[3] << 16);
    r.z = H[4] | (H[5] << 16); r.w = H[6] | (H[7] << 16);
    return r;
}

// ---------------------------------------------------------------------------
// Fused weight prep (one launch): Wt[n][k] = fp16(k<256 ? Ws[k][n] : Wn[..])
// ---------------------------------------------------------------------------
__global__ void convert_weights_all(
    const float* __restrict__ Ws0, const float* __restrict__ Wn0,
    const float* __restrict__ Ws1, const float* __restrict__ Wn1,
    const float* __restrict__ Ws2, const float* __restrict__ Wn2,
    __half* __restrict__ wt0, __half* __restrict__ wt1,
    __half* __restrict__ wt2)
{
    int idx = blockIdx.x * blockDim.x + threadIdx.x;
    const float *Ws, *Wn;
    __half* wt;
    int NC, local;
    if (idx < 131072)      { Ws = Ws0; Wn = Wn0; wt = wt0; NC = 256; local = idx; }
    else if (idx < 262144) { Ws = Ws1; Wn = Wn1; wt = wt1; NC = 256; local = idx - 131072; }
    else if (idx < 294912) { Ws = Ws2; Wn = Wn2; wt = wt2; NC = 64;  local = idx - 262144; }
    else return;
    int n = local >> 9, k = local & 511;
    float v = (k < 256) ? Ws[(size_t)k * NC + n] : Wn[(size_t)(k - 256) * NC + n];
    wt[local] = __float2half_rn(v);
}

// ---------------------------------------------------------------------------
// Edge aggregation: 4 edges/warp, batched LDG.128 gather, vector REDs (R6)
// ---------------------------------------------------------------------------
__global__ void sage_aggregate(const float* __restrict__ h,
                               const int*   __restrict__ src,
                               const int*   __restrict__ dst,
                               float*       __restrict__ agg,
                               float*       __restrict__ deg,
                               int E)
{
    int warp = (int)(blockIdx.x * (blockDim.x >> 5) + (threadIdx.x >> 5));
    int lane = threadIdx.x & 31;
    int e0 = warp * 4;
    if (e0 >= E) return;
    int n = E - e0;
    if (n > 4) n = 4;

    int s[4], d[4];
#pragma unroll
    for (int e = 0; e < 4; e++) {
        int idx = (e < n) ? e0 + e : e0;
        s[e] = __ldg(src + idx);
        d[e] = __ldg(dst + idx);
    }
    float4 v[4][2];
#pragma unroll
    for (int e = 0; e < 4; e++) {
        if (e < n) {
            const float4* hs = (const float4*)(h + (size_t)s[e] * DF) + lane;
            v[e][0] = __ldg(hs);
            v[e][1] = __ldg(hs + 32);
        }
    }
#pragma unroll
    for (int e = 0; e < 4; e++) {
        if (e < n) {
            float* p = agg + (size_t)d[e] * DF + lane * 4;
            asm volatile("red.global.add.v4.f32 [%0], {%1, %2, %3, %4};"
                         :: "l"(p), "f"(v[e][0].x), "f"(v[e][0].y),
                            "f"(v[e][0].z), "f"(v[e][0].w) : "memory");
            asm volatile("red.global.add.v4.f32 [%0], {%1, %2, %3, %4};"
                         :: "l"(p + 128), "f"(v[e][1].x), "f"(v[e][1].y),
                            "f"(v[e][1].z), "f"(v[e][1].w) : "memory");
        }
    }
#pragma unroll
    for (int e = 0; e < 4; e++)
        if (lane == e && e < n) atomicAdd(deg + d[e], 1.0f);
}

// ---------------------------------------------------------------------------
// GEMM tile, BK=64, K=256 slice of [Ws;Wn]:
//   NEIGH: A=agg scaled by 1/max(deg,1); accumulate into out; optional RELU.
//   !NEIGH: plain A; write acc + bias.
// 8 warps (4x2), warp tile 32x(BN/2). A fp32 -> regs -> fp16 smem (pitch 144
// = 128B data + 16B skew: 8 consecutive rows hit 8 distinct 16B quadrants).
// B fp16 via cp.async, double-buffered; 4 barrier iterations total.
// ---------------------------------------------------------------------------
template<int BN, bool NEIGH, bool RELU>
__device__ __forceinline__ void gemm_tile(
    const float* __restrict__ A, const float* __restrict__ deg,
    const __half* __restrict__ wt, int koff,
    const float* __restrict__ bias, float* __restrict__ out,
    int M, int NCOLS, int bm0, int bn0, char* smem)
{
    constexpr int APITCH = 144;           // 64 halves = 128B data + 16B skew
    constexpr int ASTG   = 128 * APITCH;  // 18432
    constexpr int BSTG   = BN * APITCH;
    constexpr int SS     = ASTG + BSTG;
    constexpr int NT8    = BN / 16;
    constexpr int NBSEG  = BN / 32;       // B 16B-segs per thread
    constexpr int WN     = BN / 2;

    float* s_invd = (float*)smem;
    char*  stg    = smem + 1024;
    uint32_t stg_u = smem_u32(stg);

    int tid  = threadIdx.x;
    int lane = tid & 31, wid = tid >> 5;
    int wm = wid & 3, wn = wid >> 2;

    if (NEIGH) {
        if (tid < 128) {
            int r = bm0 + tid;
            float dg = (r < M) ? deg[r] : 1.0f;
            s_invd[tid] = 1.0f / fmaxf(dg, 1.0f);
        }
        __syncthreads();
    }

    uint4 ah[4];

    auto prepA = [&](int kt) {
        int kc = kt * 64;
#pragma unroll
        for (int i = 0; i < 4; i++) {
            int seg = tid + 256 * i;          // 0..1023
            int row = seg >> 3, c8 = (seg & 7) * 8;
            int gr = bm0 + row;
            float4 v0 = make_float4(0.f, 0.f, 0.f, 0.f), v1 = v0;
            if (gr < M) {
                const float4* p = (const float4*)(A + (size_t)gr * DF + kc + c8);
                v0 = __ldg(p); v1 = __ldg(p + 1);
                if (NEIGH) {
                    float sc = s_invd[row];
                    v0.x *= sc; v0.y *= sc; v0.z *= sc; v0.w *= sc;
                    v1.x *= sc; v1.y *= sc; v1.z *= sc; v1.w *= sc;
                }
            }
            ah[i] = cvt8(v0, v1);
        }
    };

    auto storeA = [&](int s) {
        char* base = stg + s * SS;
#pragma unroll
        for (int i = 0; i < 4; i++) {
            int seg = tid + 256 * i;
            int row = seg >> 3, cc = (seg & 7) * 16;
            *(uint4*)(base + row * APITCH + cc) = ah[i];
        }
    };

    auto issueB = [&](int kt, int s) {
        int kg = kt * 64;
        uint32_t bbase = stg_u + s * SS + ASTG;
#pragma unroll
        for (int i = 0; i < NBSEG; i++) {
            int seg = tid + 256 * i;          // BN*8 segs total
            int row = seg >> 3, cc = (seg & 7) * 16;
            uint32_t sa = bbase + row * APITCH + cc;
            const __half* g = wt + (size_t)(bn0 + row) * 512 + koff + kg + (seg & 7) * 8;
            asm volatile("cp.async.cg.shared.global [%0], [%1], 16;"
                         :: "r"(sa), "l"(g));
        }
        asm volatile("cp.async.commit_group;" ::: "memory");
    };

    float acc[2][NT8][4] = {};

    issueB(0, 0);
    prepA(0);

#pragma unroll 1
    for (int kt = 0; kt < 4; kt++) {
        int s = kt & 1;
        storeA(s);
        asm volatile("cp.async.wait_group 0;" ::: "memory");
        __syncthreads();
        if (kt < 3) {
            issueB(kt + 1, 1 - s);
            prepA(kt + 1);
        }

        uint32_t abase = stg_u + s * SS;
        uint32_t bbase = abase + ASTG;
#pragma unroll
        for (int ks = 0; ks < 4; ks++) {
            uint32_t af[2][4], bf[NT8][2];
#pragma unroll
            for (int mt = 0; mt < 2; mt++) {
                int r  = wm * 32 + mt * 16 + (lane & 7) + ((lane >> 3) & 1) * 8;
                int kb = ks * 16 + ((lane >> 4) & 1) * 8;
                ldsm4(af[mt], abase + r * APITCH + kb * 2);
            }
#pragma unroll
            for (int p = 0; p < NT8 / 2; p++) {
                int n  = wn * WN + p * 16 + (lane & 7) + ((lane >> 4) & 1) * 8;
                int kb = ks * 16 + ((lane >> 3) & 1) * 8;
                uint32_t th[4];
                ldsm4(th, bbase + n * APITCH + kb * 2);
                bf[2 * p][0] = th[0]; bf[2 * p][1] = th[1];
                bf[2 * p + 1][0] = th[2]; bf[2 * p + 1][1] = th[3];
            }
#pragma unroll
            for (int mt = 0; mt < 2; mt++)
#pragma unroll
                for (int nt = 0; nt < NT8; nt++)
                    mma16816(acc[mt][nt], af[mt], bf[nt]);
        }
    }

    // ---- epilogue ----
#pragma unroll
    for (int mt = 0; mt < 2; mt++) {
        int r0 = bm0 + wm * 32 + mt * 16 + (lane >> 2);
#pragma unroll
        for (int nt = 0; nt < NT8; nt++) {
            int col = bn0 + wn * WN + nt * 8 + (lane & 3) * 2;
            float2 o0, o1;
            if (NEIGH) {
                o0.x = acc[mt][nt][0]; o0.y = acc[mt][nt][1];
                o1.x = acc[mt][nt][2]; o1.y = acc[mt][nt][3];
                if (r0 < M) {
                    float2 e = *(const float2*)(out + (size_t)r0 * NCOLS + col);
                    o0.x += e.x; o0.y += e.y;
                }
                if (r0 + 8 < M) {
                    float2 e = *(const float2*)(out + (size_t)(r0 + 8) * NCOLS + col);
                    o1.x += e.x; o1.y += e.y;
                }
                if (RELU) {
                    o0.x = fmaxf(o0.x, 0.f); o0.y = fmaxf(o0.y, 0.f);
                    o1.x = fmaxf(o1.x, 0.f); o1.y = fmaxf(o1.y, 0.f);
                }
            } else {
                float2 bv = *(const float2*)(bias + col);
                o0.x = acc[mt][nt][0] + bv.x; o0.y = acc[mt][nt][1] + bv.y;
                o1.x = acc[mt][nt][2] + bv.x; o1.y = acc[mt][nt][3] + bv.y;
            }
            if (r0 < M)
                *(float2*)(out + (size_t)r0 * NCOLS + col) = o0;
            if (r0 + 8 < M)
                *(float2*)(out + (size_t)(r0 + 8) * NCOLS + col) = o1;
        }
    }
}

template<int BN>
__global__ __launch_bounds__(256)
void sage_gemm_self(const float* __restrict__ h,
                    const __half* __restrict__ wt,
                    const float* __restrict__ bias,
                    float* __restrict__ out, int M, int NCOLS)
{
    extern __shared__ char smem[];
    gemm_tile<BN, false, false>(h, nullptr, wt, 0, bias, out, M, NCOLS,
                                blockIdx.y * 128, blockIdx.x * BN, smem);
}

template<int BN, bool RELU>
__global__ __launch_bounds__(256)
void sage_gemm_neigh(const float* __restrict__ agg,
                     const float* __restrict__ deg,
                     const __half* __restrict__ wt,
                     float* __restrict__ out, int M, int NCOLS)
{
    extern __shared__ char smem[];
    gemm_tile<BN, true, RELU>(agg, deg, wt, 256, nullptr, out, M, NCOLS,
                              blockIdx.y * 128, blockIdx.x * BN, smem);
}

// ---------------------------------------------------------------------------
// Launch: one memset, one convert; fork-join per layer.
// ---------------------------------------------------------------------------
extern "C" void kernel_launch(void* const* d_in, const int* in_sizes, int n_in,
                              void* d_out, int out_size)
{
    const float* x    = (const float*)d_in[0];
    const int*   src0 = (const int*)d_in[1];
    const int*   dst0 = (const int*)d_in[2];
    const int*   src1 = (const int*)d_in[3];
    const int*   dst1 = (const int*)d_in[4];
    const int*   src2 = (const int*)d_in[5];
    const int*   dst2 = (const int*)d_in[6];

    int wb = n_in - 9;
    const float* Ws0 = (const float*)d_in[wb + 0];
    const float* Wn0 = (const float*)d_in[wb + 1];
    const float* b0  = (const float*)d_in[wb + 2];
    const float* Ws1 = (const float*)d_in[wb + 3];
    const float* Wn1 = (const float*)d_in[wb + 4];
    const float* b1  = (const float*)d_in[wb + 5];
    const float* Ws2 = (const float*)d_in[wb + 6];
    const float* Wn2 = (const float*)d_in[wb + 7];
    const float* b2  = (const float*)d_in[wb + 8];

    int E0 = in_sizes[1];
    int E1 = in_sizes[3];
    int E2 = in_sizes[5];

    float *scr, *h1, *h2;
    __half *wt0, *wt1, *wt2;
    cudaGetSymbolAddress((void**)&scr, g_scr);
    cudaGetSymbolAddress((void**)&h1,  g_h1);
    cudaGetSymbolAddress((void**)&h2,  g_h2);
    cudaGetSymbolAddress((void**)&wt0, g_wt0);
    cudaGetSymbolAddress((void**)&wt1, g_wt1);
    cudaGetSymbolAddress((void**)&wt2, g_wt2);

    float* agg0 = scr + AGG0_OFF;
    float* agg1 = scr + AGG1_OFF;
    float* agg2 = scr + AGG2_OFF;
    float* deg0 = scr + DEG0_OFF;
    float* deg1 = scr + DEG1_OFF;
    float* deg2 = scr + DEG2_OFF;

    // dynamic smem: 1024 + 2 stages of (A 18432 + B BN*144)
    const int SMEM128 = 1024 + 2 * (18432 + 128 * 144);  // 74752
    const int SMEM64  = 1024 + 2 * (18432 + 64 * 144);   // 56320
    cudaFuncSetAttribute(sage_gemm_self<128>,
                         cudaFuncAttributeMaxDynamicSharedMemorySize, SMEM128);
    cudaFuncSetAttribute(sage_gemm_self<64>,
                         cudaFuncAttributeMaxDynamicSharedMemorySize, SMEM64);
    cudaFuncSetAttribute(sage_gemm_neigh<128, false>,
                         cudaFuncAttributeMaxDynamicSharedMemorySize, SMEM128);
    cudaFuncSetAttribute(sage_gemm_neigh<128, true>,
                         cudaFuncAttributeMaxDynamicSharedMemorySize, SMEM128);
    cudaFuncSetAttribute(sage_gemm_neigh<64, false>,
                         cudaFuncAttributeMaxDynamicSharedMemorySize, SMEM64);

    cudaStream_t s2;
    cudaStreamCreateWithFlags(&s2, cudaStreamNonBlocking);
    cudaEvent_t evStart, evJ0, evJ1, evJ2, evN0, evN1;
    cudaEventCreateWithFlags(&evStart, cudaEventDisableTiming);
    cudaEventCreateWithFlags(&evJ0,    cudaEventDisableTiming);
    cudaEventCreateWithFlags(&evJ1,    cudaEventDisableTiming);
    cudaEventCreateWithFlags(&evJ2,    cudaEventDisableTiming);
    cudaEventCreateWithFlags(&evN0,    cudaEventDisableTiming);
    cudaEventCreateWithFlags(&evN1,    cudaEventDisableTiming);

    // fork: s2 converts weights + runs self-GEMMs; default owns agg + neigh
    cudaEventRecord(evStart, 0);
    cudaStreamWaitEvent(s2, evStart, 0);

    // default: single memset then straight into aggregation
    cudaMemsetAsync(scr, 0, sizeof(float) * (size_t)SCR_TOT);

    // s2: fused weight convert, then self0 (needs only x + wt0)
    convert_weights_all<<<(294912 + 255) / 256, 256, 0, s2>>>(
        Ws0, Wn0, Ws1, Wn1, Ws2, Wn2, wt0, wt1, wt2);
    sage_gemm_self<128><<<dim3(2, (N1C + 127) / 128), 256, SMEM128, s2>>>(
        x, wt0, b0, h1, N1C, 256);
    cudaEventRecord(evJ0, s2);

    // ---- Layer 0 ----
    sage_aggregate<<<(E0 + 31) / 32, 256>>>(x, src0, dst0, agg0, deg0, E0);
    cudaStreamWaitEvent(0, evJ0, 0);
    sage_gemm_neigh<128, false><<<dim3(2, (N1C + 127) / 128), 256, SMEM128>>>(
        agg0, deg0, wt0, h1, N1C, 256);
    cudaEventRecord(evN0, 0);

    // s2: self1 after h1 complete
    cudaStreamWaitEvent(s2, evN0, 0);
    sage_gemm_self<128><<<dim3(2, (N2C + 127) / 128), 256, SMEM128, s2>>>(
        h1, wt1, b1, h2, N2C, 256);
    cudaEventRecord(evJ1, s2);

    // ---- Layer 1 (relu) ----
    sage_aggregate<<<(E1 + 31) / 32, 256>>>(h1, src1, dst1, agg1, deg1, E1);
    cudaStreamWaitEvent(0, evJ1, 0);
    sage_gemm_neigh<128, true><<<dim3(2, (N2C + 127) / 128), 256, SMEM128>>>(
        agg1, deg1, wt1, h2, N2C, 256);
    cudaEventRecord(evN1, 0);

    // s2: self2 after h2 complete
    cudaStreamWaitEvent(s2, evN1, 0);
    sage_gemm_self<64><<<dim3(1, (N3C + 127) / 128), 256, SMEM64, s2>>>(
        h2, wt2, b2, (float*)d_out, N3C, 64);
    cudaEventRecord(evJ2, s2);

    // ---- Layer 2 ----
    sage_aggregate<<<(E2 + 31) / 32, 256>>>(h2, src2, dst2, agg2, deg2, E2);
    cudaStreamWaitEvent(0, evJ2, 0);
    sage_gemm_neigh<64, false><<<dim3(1, (N3C + 127) / 128), 256, SMEM64>>>(
        agg2, deg2, wt2, (float*)d_out, N3C, 64);
}